// round 1
// baseline (speedup 1.0000x reference)
#include <cuda_runtime.h>
#include <math.h>

#define NATOM 2048
#define NTOK  512
#define CDIM  128
#define CZD   16
#define NHEADS 4
#define CHD   32
#define NBL   3
#define NHID  256
#define NQ    32
#define NKEY  128
#define NQB   (NATOM/NQ)      /* 64 query blocks */
#define EPS   1e-5f
#define NEGBIG -1e30f

// ---------------- scratch (device globals; no allocation allowed) ----------------
__device__ float g_maskbias[NATOM];
__device__ float g_lns[NATOM*CDIM];
__device__ float g_gate1[NBL*NATOM*CDIM];
__device__ float g_shift1[NBL*NATOM*CDIM];
__device__ float g_gate2[NBL*NATOM*CDIM];
__device__ float g_shift2[NBL*NATOM*CDIM];
__device__ float g_og1[NBL*NATOM*CDIM];
__device__ float g_og2[NBL*NATOM*CDIM];
__device__ float g_pb[NBL*NHEADS*NATOM*NKEY];   // [b*4+h][n][slot], mask+window folded
__device__ float g_a[NATOM*CDIM];
__device__ float g_an[NATOM*CDIM];
__device__ float g_q[NATOM*CDIM];
__device__ float g_k[NATOM*CDIM];
__device__ float g_v[NATOM*CDIM];
__device__ float g_g[NATOM*CDIM];
__device__ float g_ob[NATOM*CDIM];
__device__ float g_attout[NATOM*CDIM];
__device__ float g_hidden[NATOM*NHID];

__device__ __forceinline__ float sigm(float x){ return 1.f/(1.f+expf(-x)); }

// ---------------- copy in/out ----------------
__global__ void copy_in_kernel(const float* __restrict__ src){
    int i = blockIdx.x*256 + threadIdx.x;
    g_a[i] = src[i];
}
__global__ void copy_out_kernel(float* __restrict__ dst){
    int i = blockIdx.x*256 + threadIdx.x;
    dst[i] = g_a[i];
}

// ---------------- mask bias: (sum_i a2t[n,i]*tm[i] - 1) * 1e9 ----------------
__global__ void maskbias_kernel(const float* __restrict__ a2t, const float* __restrict__ tm){
    int w = threadIdx.x >> 5, l = threadIdx.x & 31;
    int n = blockIdx.x*8 + w;
    const float* row = a2t + (size_t)n*NTOK;
    float s = 0.f;
    for (int i = l; i < NTOK; i += 32) s += row[i]*tm[i];
    #pragma unroll
    for (int o = 16; o; o >>= 1) s += __shfl_xor_sync(0xffffffffu, s, o);
    if (l == 0) g_maskbias[n] = (s - 1.0f)*1e9f;
}

// ---------------- LN(cl) -> g_lns ----------------
__global__ void ln_cl_kernel(const float* __restrict__ in){
    int w = threadIdx.x >> 5, l = threadIdx.x & 31;
    int base = blockIdx.x*16 + w*4;
    for (int r = 0; r < 4; r++){
        const float* row = in + (size_t)(base+r)*CDIM;
        float x0=row[l], x1=row[l+32], x2=row[l+64], x3=row[l+96];
        float s = x0+x1+x2+x3;
        float s2 = x0*x0+x1*x1+x2*x2+x3*x3;
        #pragma unroll
        for (int o = 16; o; o >>= 1){
            s  += __shfl_xor_sync(0xffffffffu, s, o);
            s2 += __shfl_xor_sync(0xffffffffu, s2, o);
        }
        float mean = s*(1.f/CDIM);
        float var  = s2*(1.f/CDIM) - mean*mean;
        float rstd = rsqrtf(var + EPS);
        float* orow = g_lns + (size_t)(base+r)*CDIM;
        orow[l]    = (x0-mean)*rstd;
        orow[l+32] = (x1-mean)*rstd;
        orow[l+64] = (x2-mean)*rstd;
        orow[l+96] = (x3-mean)*rstd;
    }
}

// ---------------- generic 2048x128 @ 128x128 with optional gs scale / bias / sigmoid ----
__global__ void gate_gemm_kernel(const float* __restrict__ in, const float* __restrict__ gs,
                                 const float* __restrict__ W, const float* __restrict__ bias,
                                 float* __restrict__ out, int sig){
    __shared__ float ins[16][CDIM];
    int t = threadIdx.x; int m0 = blockIdx.x*16;
    for (int idx = t; idx < 16*CDIM; idx += 128){
        int r = idx >> 7, c = idx & 127;
        float v = in[(size_t)(m0+r)*CDIM + c];
        if (gs) v *= gs[c];
        ins[r][c] = v;
    }
    __syncthreads();
    float acc[16];
    #pragma unroll
    for (int i = 0; i < 16; i++) acc[i] = 0.f;
    #pragma unroll 4
    for (int k = 0; k < CDIM; k++){
        float w = W[k*CDIM + t];
        #pragma unroll
        for (int i = 0; i < 16; i++) acc[i] += ins[i][k]*w;
    }
    float b = bias ? bias[t] : 0.f;
    #pragma unroll
    for (int i = 0; i < 16; i++){
        float v = acc[i] + b;
        if (sig) v = sigm(v);
        out[(size_t)(m0+i)*CDIM + t] = v;
    }
}

// ---------------- pair bias: LN over cz of plm window, x (gz*wz) for all (b,h); mask folded ----
__global__ void pb_kernel(const float* __restrict__ plm, const float* __restrict__ gz,
                          const float* __restrict__ bz, const float* __restrict__ wz){
    __shared__ float wzc[CZD][12];
    __shared__ float bzd[12];
    int t = threadIdx.x;
    if (t < CZD*12){
        int c = t/12, idx = t%12, b = idx>>2, h = idx&3;
        wzc[c][idx] = gz[b*CZD + c]*wz[(b*CZD + c)*4 + h];
    }
    if (t < 12){
        int b = t>>2, h = t&3; float s = 0.f;
        for (int c = 0; c < CZD; c++) s += bz[b*CZD + c]*wz[(b*CZD + c)*4 + h];
        bzd[t] = s;
    }
    __syncthreads();
    int gid = blockIdx.x*256 + t;
    int n = gid >> 7, slot = gid & 127;
    int m = (n & ~31) - 48 + slot;
    if (m < 0 || m >= NATOM){
        #pragma unroll
        for (int idx = 0; idx < 12; idx++)
            g_pb[((size_t)idx*NATOM + n)*NKEY + slot] = NEGBIG;
        return;
    }
    const float4* p = (const float4*)(plm + ((size_t)n*NATOM + m)*CZD);
    float x[16];
    float4 f;
    f = p[0]; x[0]=f.x; x[1]=f.y; x[2]=f.z; x[3]=f.w;
    f = p[1]; x[4]=f.x; x[5]=f.y; x[6]=f.z; x[7]=f.w;
    f = p[2]; x[8]=f.x; x[9]=f.y; x[10]=f.z; x[11]=f.w;
    f = p[3]; x[12]=f.x; x[13]=f.y; x[14]=f.z; x[15]=f.w;
    float s = 0.f, s2 = 0.f;
    #pragma unroll
    for (int c = 0; c < 16; c++){ s += x[c]; s2 += x[c]*x[c]; }
    float mean = s*(1.f/16.f);
    float var  = s2*(1.f/16.f) - mean*mean;
    float rstd = rsqrtf(var + EPS);
    float val[12];
    #pragma unroll
    for (int idx = 0; idx < 12; idx++) val[idx] = 0.f;
    #pragma unroll
    for (int c = 0; c < 16; c++){
        float z = (x[c]-mean)*rstd;
        #pragma unroll
        for (int idx = 0; idx < 12; idx++) val[idx] += z*wzc[c][idx];
    }
    float mb = g_maskbias[m];
    #pragma unroll
    for (int idx = 0; idx < 12; idx++)
        g_pb[((size_t)idx*NATOM + n)*NKEY + slot] = val[idx] + bzd[idx] + mb;
}

// ---------------- per-block: AdaLN(a) then q,k,v,g projections ----------------
__global__ void adaln_qkvg_kernel(const float* __restrict__ gate1, const float* __restrict__ shift1,
                                  const float* __restrict__ wq, const float* __restrict__ bq,
                                  const float* __restrict__ wk, const float* __restrict__ wv,
                                  const float* __restrict__ wg){
    __shared__ float als[16][CDIM];
    int t = threadIdx.x; int m0 = blockIdx.x*16;
    int w = t >> 5, l = t & 31;
    for (int idx = t; idx < 16*CDIM; idx += 128){
        int r = idx >> 7, c = idx & 127;
        als[r][c] = g_a[(size_t)(m0+r)*CDIM + c];
    }
    __syncthreads();
    for (int r = 0; r < 4; r++){
        int i = w*4 + r; int n = m0 + i;
        float x0=als[i][l], x1=als[i][l+32], x2=als[i][l+64], x3=als[i][l+96];
        float s = x0+x1+x2+x3;
        float s2 = x0*x0+x1*x1+x2*x2+x3*x3;
        #pragma unroll
        for (int o = 16; o; o >>= 1){
            s  += __shfl_xor_sync(0xffffffffu, s, o);
            s2 += __shfl_xor_sync(0xffffffffu, s2, o);
        }
        float mean = s*(1.f/CDIM);
        float var  = s2*(1.f/CDIM) - mean*mean;
        float rstd = rsqrtf(var + EPS);
        float a0=(x0-mean)*rstd, a1=(x1-mean)*rstd, a2=(x2-mean)*rstd, a3=(x3-mean)*rstd;
        size_t nb = (size_t)n*CDIM;
        g_an[nb+l]=a0; g_an[nb+l+32]=a1; g_an[nb+l+64]=a2; g_an[nb+l+96]=a3;
        als[i][l]    = gate1[nb+l]   *a0 + shift1[nb+l];
        als[i][l+32] = gate1[nb+l+32]*a1 + shift1[nb+l+32];
        als[i][l+64] = gate1[nb+l+64]*a2 + shift1[nb+l+64];
        als[i][l+96] = gate1[nb+l+96]*a3 + shift1[nb+l+96];
    }
    __syncthreads();
    const float* Ws[4] = {wq, wk, wv, wg};
    float* Os[4] = {g_q, g_k, g_v, g_g};
    for (int mat = 0; mat < 4; mat++){
        float acc[16];
        #pragma unroll
        for (int i = 0; i < 16; i++) acc[i] = 0.f;
        const float* W = Ws[mat];
        #pragma unroll 4
        for (int k = 0; k < CDIM; k++){
            float wv_ = W[k*CDIM + t];
            #pragma unroll
            for (int i = 0; i < 16; i++) acc[i] += als[i][k]*wv_;
        }
        #pragma unroll
        for (int i = 0; i < 16; i++){
            float v = acc[i];
            if (mat == 0) v += bq[t];
            if (mat == 3) v = sigm(v);
            Os[mat][(size_t)(m0+i)*CDIM + t] = v;
        }
    }
}

// ---------------- block-sparse attention: 32 queries x 128-key window per CTA ----------------
__global__ void attn_kernel(const float* __restrict__ pb){
    __shared__ float qs[32][32];
    __shared__ float vs[128][32];
    __shared__ float buf[128*32];   // first K tile, then logits [32][128]
    int t = threadIdx.x;
    int j = blockIdx.x, h = blockIdx.y;
    int n0 = j*NQ, w0 = j*NQ - 48, hd0 = h*CHD;
    for (int idx = t; idx < 32*32; idx += 128){
        int i = idx >> 5, d = idx & 31;
        qs[i][d] = g_q[(size_t)(n0+i)*CDIM + hd0 + d];
    }
    for (int idx = t; idx < 128*32; idx += 128){
        int m = idx >> 5, d = idx & 31;
        int key = w0 + m;
        float kk = 0.f, vv = 0.f;
        if (key >= 0 && key < NATOM){
            kk = g_k[(size_t)key*CDIM + hd0 + d];
            vv = g_v[(size_t)key*CDIM + hd0 + d];
        }
        buf[m*32 + d] = kk; vs[m][d] = vv;
    }
    __syncthreads();
    float kr[32];
    #pragma unroll
    for (int d = 0; d < 32; d++) kr[d] = buf[t*32 + d];
    __syncthreads();
    const float scale = 0.17677669529663687f;  // 1/sqrt(32)
    const float* pbr = pb + (size_t)h*NATOM*NKEY + (size_t)n0*NKEY;
    for (int i = 0; i < 32; i++){
        float acc = 0.f;
        #pragma unroll
        for (int d = 0; d < 32; d++) acc += qs[i][d]*kr[d];
        buf[i*128 + t] = acc*scale + pbr[i*NKEY + t];
    }
    __syncthreads();
    int w = t >> 5, l = t & 31;
    for (int r = 0; r < 8; r++){
        int i = w*8 + r;
        float x0=buf[i*128+l], x1=buf[i*128+l+32], x2=buf[i*128+l+64], x3=buf[i*128+l+96];
        float mx = fmaxf(fmaxf(x0,x1), fmaxf(x2,x3));
        #pragma unroll
        for (int o = 16; o; o >>= 1) mx = fmaxf(mx, __shfl_xor_sync(0xffffffffu, mx, o));
        float e0=expf(x0-mx), e1=expf(x1-mx), e2=expf(x2-mx), e3=expf(x3-mx);
        float s = e0+e1+e2+e3;
        #pragma unroll
        for (int o = 16; o; o >>= 1) s += __shfl_xor_sync(0xffffffffu, s, o);
        float inv = 1.f/s;
        buf[i*128+l]=e0*inv; buf[i*128+l+32]=e1*inv; buf[i*128+l+64]=e2*inv; buf[i*128+l+96]=e3*inv;
    }
    __syncthreads();
    int i = t >> 2, d0 = (t & 3)*8;
    float acc[8];
    #pragma unroll
    for (int dd = 0; dd < 8; dd++) acc[dd] = 0.f;
    #pragma unroll 4
    for (int kk = 0; kk < 128; kk++){
        float wgt = buf[i*128 + kk];
        #pragma unroll
        for (int dd = 0; dd < 8; dd++) acc[dd] += wgt*vs[kk][d0+dd];
    }
    int n = n0 + i;
    #pragma unroll
    for (int dd = 0; dd < 8; dd++){
        int c = hd0 + d0 + dd;
        g_ob[(size_t)n*CDIM + c] = g_g[(size_t)n*CDIM + c]*acc[dd];
    }
}

// ---------------- out projection * og1 gate ----------------
__global__ void outproj_kernel(const float* __restrict__ wo, const float* __restrict__ og1){
    __shared__ float ins[16][CDIM];
    int t = threadIdx.x; int m0 = blockIdx.x*16;
    for (int idx = t; idx < 16*CDIM; idx += 128){
        int r = idx >> 7, c = idx & 127;
        ins[r][c] = g_ob[(size_t)(m0+r)*CDIM + c];
    }
    __syncthreads();
    float acc[16];
    #pragma unroll
    for (int i = 0; i < 16; i++) acc[i] = 0.f;
    #pragma unroll 4
    for (int k = 0; k < CDIM; k++){
        float w = wo[k*CDIM + t];
        #pragma unroll
        for (int i = 0; i < 16; i++) acc[i] += ins[i][k]*w;
    }
    #pragma unroll
    for (int i = 0; i < 16; i++){
        size_t o = (size_t)(m0+i)*CDIM + t;
        g_attout[o] = og1[o]*acc[i];
    }
}

// ---------------- transition part 1: a2 -> silu(a2@wt1)*(a2@wt2) ----------------
__global__ void trans1_kernel(const float* __restrict__ gate2, const float* __restrict__ shift2,
                              const float* __restrict__ wt1, const float* __restrict__ wt2){
    __shared__ float a2s[16][CDIM];
    int t = threadIdx.x;   // 256 threads
    int m0 = blockIdx.x*16;
    for (int idx = t; idx < 16*CDIM; idx += 256){
        int r = idx >> 7, c = idx & 127;
        size_t o = (size_t)(m0+r)*CDIM + c;
        a2s[r][c] = gate2[o]*g_an[o] + shift2[o];
    }
    __syncthreads();
    float acc1[16], acc2[16];
    #pragma unroll
    for (int i = 0; i < 16; i++){ acc1[i]=0.f; acc2[i]=0.f; }
    #pragma unroll 2
    for (int k = 0; k < CDIM; k++){
        float w1 = wt1[k*NHID + t], w2 = wt2[k*NHID + t];
        #pragma unroll
        for (int i = 0; i < 16; i++){
            float a = a2s[i][k];
            acc1[i] += a*w1; acc2[i] += a*w2;
        }
    }
    #pragma unroll
    for (int i = 0; i < 16; i++){
        float h1 = acc1[i];
        float sw = h1*sigm(h1);
        g_hidden[(size_t)(m0+i)*NHID + t] = sw*acc2[i];
    }
}

// ---------------- transition part 2: hidden@wt3 * og2 + attout -> a ----------------
__global__ void trans2_kernel(const float* __restrict__ wt3, const float* __restrict__ og2){
    __shared__ float hs[16][NHID];
    int t = threadIdx.x;   // 128
    int m0 = blockIdx.x*16;
    for (int idx = t; idx < 16*NHID; idx += 128){
        int r = idx >> 8, c = idx & 255;
        hs[r][c] = g_hidden[(size_t)(m0+r)*NHID + c];
    }
    __syncthreads();
    float acc[16];
    #pragma unroll
    for (int i = 0; i < 16; i++) acc[i] = 0.f;
    #pragma unroll 4
    for (int k = 0; k < NHID; k++){
        float w = wt3[k*CDIM + t];
        #pragma unroll
        for (int i = 0; i < 16; i++) acc[i] += hs[i][k]*w;
    }
    #pragma unroll
    for (int i = 0; i < 16; i++){
        size_t o = (size_t)(m0+i)*CDIM + t;
        g_a[o] = g_attout[o] + og2[o]*acc[i];
    }
}

// ---------------- host launcher ----------------
extern "C" void kernel_launch(void* const* d_in, const int* in_sizes, int n_in,
                              void* d_out, int out_size){
    const float* ql       = (const float*)d_in[0];
    const float* cl       = (const float*)d_in[1];
    const float* plm      = (const float*)d_in[2];
    const float* a2t      = (const float*)d_in[3];
    const float* tm       = (const float*)d_in[4];
    const float* ada1_gs  = (const float*)d_in[5];
    const float* ada1_ws  = (const float*)d_in[6];
    const float* ada1_bs  = (const float*)d_in[7];
    const float* ada1_wsb = (const float*)d_in[8];
    const float* wq       = (const float*)d_in[9];
    const float* bq       = (const float*)d_in[10];
    const float* wk       = (const float*)d_in[11];
    const float* wv       = (const float*)d_in[12];
    const float* gz       = (const float*)d_in[13];
    const float* bz       = (const float*)d_in[14];
    const float* wz       = (const float*)d_in[15];
    const float* wg       = (const float*)d_in[16];
    const float* wo       = (const float*)d_in[17];
    const float* wog1     = (const float*)d_in[18];
    const float* bog1     = (const float*)d_in[19];
    const float* ada2_gs  = (const float*)d_in[20];
    const float* ada2_ws  = (const float*)d_in[21];
    const float* ada2_bs  = (const float*)d_in[22];
    const float* ada2_wsb = (const float*)d_in[23];
    const float* wt1      = (const float*)d_in[24];
    const float* wt2      = (const float*)d_in[25];
    const float* wt3      = (const float*)d_in[26];
    const float* wog2     = (const float*)d_in[27];
    const float* bog2     = (const float*)d_in[28];

    float *p_lns, *p_gate1, *p_shift1, *p_gate2, *p_shift2, *p_og1, *p_og2, *p_pb;
    cudaGetSymbolAddress((void**)&p_lns,    g_lns);
    cudaGetSymbolAddress((void**)&p_gate1,  g_gate1);
    cudaGetSymbolAddress((void**)&p_shift1, g_shift1);
    cudaGetSymbolAddress((void**)&p_gate2,  g_gate2);
    cudaGetSymbolAddress((void**)&p_shift2, g_shift2);
    cudaGetSymbolAddress((void**)&p_og1,    g_og1);
    cudaGetSymbolAddress((void**)&p_og2,    g_og2);
    cudaGetSymbolAddress((void**)&p_pb,     g_pb);

    copy_in_kernel<<<NATOM*CDIM/256, 256>>>(ql);
    maskbias_kernel<<<NATOM/8, 256>>>(a2t, tm);
    ln_cl_kernel<<<NATOM/16, 128>>>(cl);

    for (int b = 0; b < NBL; b++){
        size_t o128 = (size_t)b*CDIM, oW = (size_t)b*CDIM*CDIM, oC = (size_t)b*NATOM*CDIM;
        gate_gemm_kernel<<<NATOM/16, 128>>>(p_lns, ada1_gs+o128, ada1_ws +oW, ada1_bs+o128, p_gate1+oC, 1);
        gate_gemm_kernel<<<NATOM/16, 128>>>(p_lns, ada1_gs+o128, ada1_wsb+oW, (const float*)0, p_shift1+oC, 0);
        gate_gemm_kernel<<<NATOM/16, 128>>>(p_lns, ada2_gs+o128, ada2_ws +oW, ada2_bs+o128, p_gate2+oC, 1);
        gate_gemm_kernel<<<NATOM/16, 128>>>(p_lns, ada2_gs+o128, ada2_wsb+oW, (const float*)0, p_shift2+oC, 0);
        gate_gemm_kernel<<<NATOM/16, 128>>>(cl, (const float*)0, wog1+oW, bog1+o128, p_og1+oC, 1);
        gate_gemm_kernel<<<NATOM/16, 128>>>(cl, (const float*)0, wog2+oW, bog2+o128, p_og2+oC, 1);
    }
    pb_kernel<<<NATOM*NKEY/256, 256>>>(plm, gz, bz, wz);

    for (int b = 0; b < NBL; b++){
        size_t oC = (size_t)b*NATOM*CDIM, oW = (size_t)b*CDIM*CDIM;
        adaln_qkvg_kernel<<<NATOM/16, 128>>>(p_gate1+oC, p_shift1+oC,
                                             wq+oW, bq+(size_t)b*CDIM, wk+oW, wv+oW, wg+oW);
        dim3 ag(NQB, NHEADS);
        attn_kernel<<<ag, 128>>>(p_pb + (size_t)b*NHEADS*NATOM*NKEY);
        outproj_kernel<<<NATOM/16, 128>>>(wo+oW, p_og1+oC);
        trans1_kernel<<<NATOM/16, 256>>>(p_gate2+oC, p_shift2+oC,
                                         wt1+(size_t)b*CDIM*NHID, wt2+(size_t)b*CDIM*NHID);
        trans2_kernel<<<NATOM/16, 128>>>(wt3+(size_t)b*NHID*CDIM, p_og2+oC);
    }
    copy_out_kernel<<<NATOM*CDIM/256, 256>>>((float*)d_out);
}

// round 2
// speedup vs baseline: 2.0899x; 2.0899x over previous
#include <cuda_runtime.h>
#include <math.h>

#define NATOM 2048
#define NTOK  512
#define CDIM  128
#define CZD   16
#define NHEADS 4
#define CHD   32
#define NBL   3
#define NHID  256
#define NQ    32
#define NKEY  128
#define NQB   (NATOM/NQ)
#define EPS   1e-5f
#define NEGBIG -1e30f
#define NC    (NATOM*CDIM)

// ---------------- scratch ----------------
__device__ float g_maskbias[NATOM];
__device__ float g_lns[NC];
__device__ float g_gate1[NBL*NC];
__device__ float g_shift1[NBL*NC];
__device__ float g_gate2[NBL*NC];
__device__ float g_shift2[NBL*NC];
__device__ float g_og1[NBL*NC];
__device__ float g_og2[NBL*NC];
__device__ float g_pb[NBL*NHEADS*NATOM*NKEY];
__device__ float g_a[NC];
__device__ float g_an[NC];
__device__ float g_q[NC];
__device__ float g_k[NC];
__device__ float g_v[NC];
__device__ float g_g[NC];
__device__ float g_ob[NC];

__device__ __forceinline__ float sigm(float x){ return 1.f/(1.f+expf(-x)); }

// ---------------- copy in/out ----------------
__global__ void copy_in_kernel(const float* __restrict__ src){
    int i = blockIdx.x*256 + threadIdx.x;
    g_a[i] = src[i];
}
__global__ void copy_out_kernel(float* __restrict__ dst){
    int i = blockIdx.x*256 + threadIdx.x;
    dst[i] = g_a[i];
}

// ---------------- mask bias ----------------
__global__ void maskbias_kernel(const float* __restrict__ a2t, const float* __restrict__ tm){
    int w = threadIdx.x >> 5, l = threadIdx.x & 31;
    int n = blockIdx.x*8 + w;
    const float* row = a2t + (size_t)n*NTOK;
    float s = 0.f;
    for (int i = l; i < NTOK; i += 32) s += row[i]*tm[i];
    #pragma unroll
    for (int o = 16; o; o >>= 1) s += __shfl_xor_sync(0xffffffffu, s, o);
    if (l == 0) g_maskbias[n] = (s - 1.0f)*1e9f;
}

// ---------------- LN(cl) ----------------
__global__ void ln_cl_kernel(const float* __restrict__ in){
    int w = threadIdx.x >> 5, l = threadIdx.x & 31;
    int base = blockIdx.x*16 + w*4;
    for (int r = 0; r < 4; r++){
        const float* row = in + (size_t)(base+r)*CDIM;
        float x0=row[l], x1=row[l+32], x2=row[l+64], x3=row[l+96];
        float s = x0+x1+x2+x3;
        float s2 = x0*x0+x1*x1+x2*x2+x3*x3;
        #pragma unroll
        for (int o = 16; o; o >>= 1){
            s  += __shfl_xor_sync(0xffffffffu, s, o);
            s2 += __shfl_xor_sync(0xffffffffu, s2, o);
        }
        float mean = s*(1.f/CDIM);
        float var  = s2*(1.f/CDIM) - mean*mean;
        float rstd = rsqrtf(var + EPS);
        float* orow = g_lns + (size_t)(base+r)*CDIM;
        orow[l]    = (x0-mean)*rstd;
        orow[l+32] = (x1-mean)*rstd;
        orow[l+64] = (x2-mean)*rstd;
        orow[l+96] = (x3-mean)*rstd;
    }
}

// ---------------- batched precompute: 18 GEMMs (6 mats x 3 blocks) in ONE launch ----
__global__ void pre_gemm_kernel(const float* __restrict__ lns, const float* __restrict__ cl,
    const float* __restrict__ a1gs, const float* __restrict__ a1ws,
    const float* __restrict__ a1bs, const float* __restrict__ a1wsb,
    const float* __restrict__ a2gs, const float* __restrict__ a2ws,
    const float* __restrict__ a2bs, const float* __restrict__ a2wsb,
    const float* __restrict__ wog1, const float* __restrict__ bog1,
    const float* __restrict__ wog2, const float* __restrict__ bog2)
{
    int my = blockIdx.y;
    int b = my/6, m = my%6;
    size_t oW = (size_t)b*CDIM*CDIM, o1 = (size_t)b*CDIM, oC = (size_t)b*NC;
    const float* in = lns; const float* gs = 0; const float* W = 0;
    const float* bias = 0; float* out = 0; int sig = 0;
    switch(m){
        case 0: gs=a1gs+o1; W=a1ws +oW; bias=a1bs+o1; sig=1; out=g_gate1 +oC; break;
        case 1: gs=a1gs+o1; W=a1wsb+oW;               sig=0; out=g_shift1+oC; break;
        case 2: gs=a2gs+o1; W=a2ws +oW; bias=a2bs+o1; sig=1; out=g_gate2 +oC; break;
        case 3: gs=a2gs+o1; W=a2wsb+oW;               sig=0; out=g_shift2+oC; break;
        case 4: in=cl; W=wog1+oW; bias=bog1+o1; sig=1; out=g_og1+oC; break;
        default: in=cl; W=wog2+oW; bias=bog2+o1; sig=1; out=g_og2+oC; break;
    }
    __shared__ float ins[16][CDIM];
    int t = threadIdx.x; int m0 = blockIdx.x*16;
    for (int idx = t; idx < 16*CDIM; idx += 128){
        int r = idx >> 7, c = idx & 127;
        float v = in[(size_t)(m0+r)*CDIM + c];
        if (gs) v *= gs[c];
        ins[r][c] = v;
    }
    __syncthreads();
    float acc[16];
    #pragma unroll
    for (int i = 0; i < 16; i++) acc[i] = 0.f;
    #pragma unroll 4
    for (int k = 0; k < CDIM; k++){
        float w = W[k*CDIM + t];
        #pragma unroll
        for (int i = 0; i < 16; i++) acc[i] += ins[i][k]*w;
    }
    float bb = bias ? bias[t] : 0.f;
    #pragma unroll
    for (int i = 0; i < 16; i++){
        float v = acc[i] + bb;
        if (sig) v = sigm(v);
        out[(size_t)(m0+i)*CDIM + t] = v;
    }
}

// ---------------- pair bias (mask + window folded) ----------------
__global__ void pb_kernel(const float* __restrict__ plm, const float* __restrict__ gz,
                          const float* __restrict__ bz, const float* __restrict__ wz){
    __shared__ float wzc[CZD][12];
    __shared__ float bzd[12];
    int t = threadIdx.x;
    if (t < CZD*12){
        int c = t/12, idx = t%12, b = idx>>2, h = idx&3;
        wzc[c][idx] = gz[b*CZD + c]*wz[(b*CZD + c)*4 + h];
    }
    if (t < 12){
        int b = t>>2, h = t&3; float s = 0.f;
        for (int c = 0; c < CZD; c++) s += bz[b*CZD + c]*wz[(b*CZD + c)*4 + h];
        bzd[t] = s;
    }
    __syncthreads();
    int gid = blockIdx.x*256 + t;
    int n = gid >> 7, slot = gid & 127;
    int m = (n & ~31) - 48 + slot;
    if (m < 0 || m >= NATOM){
        #pragma unroll
        for (int idx = 0; idx < 12; idx++)
            g_pb[((size_t)idx*NATOM + n)*NKEY + slot] = NEGBIG;
        return;
    }
    const float4* p = (const float4*)(plm + ((size_t)n*NATOM + m)*CZD);
    float x[16];
    float4 f;
    f = p[0]; x[0]=f.x; x[1]=f.y; x[2]=f.z; x[3]=f.w;
    f = p[1]; x[4]=f.x; x[5]=f.y; x[6]=f.z; x[7]=f.w;
    f = p[2]; x[8]=f.x; x[9]=f.y; x[10]=f.z; x[11]=f.w;
    f = p[3]; x[12]=f.x; x[13]=f.y; x[14]=f.z; x[15]=f.w;
    float s = 0.f, s2 = 0.f;
    #pragma unroll
    for (int c = 0; c < 16; c++){ s += x[c]; s2 += x[c]*x[c]; }
    float mean = s*(1.f/16.f);
    float var  = s2*(1.f/16.f) - mean*mean;
    float rstd = rsqrtf(var + EPS);
    float val[12];
    #pragma unroll
    for (int idx = 0; idx < 12; idx++) val[idx] = 0.f;
    #pragma unroll
    for (int c = 0; c < 16; c++){
        float z = (x[c]-mean)*rstd;
        #pragma unroll
        for (int idx = 0; idx < 12; idx++) val[idx] += z*wzc[c][idx];
    }
    float mb = g_maskbias[m];
    #pragma unroll
    for (int idx = 0; idx < 12; idx++)
        g_pb[((size_t)idx*NATOM + n)*NKEY + slot] = val[idx] + bzd[idx] + mb;
}

// ---------------- per-block: fused AdaLN + one of {q,k,v,g} projections ------------
// grid(128, 4): blockIdx.y selects the matrix; LN recomputed per mat (cheap).
__global__ void adaln_proj_kernel(const float* __restrict__ gate1, const float* __restrict__ shift1,
                                  const float* __restrict__ wq, const float* __restrict__ bq,
                                  const float* __restrict__ wk, const float* __restrict__ wv,
                                  const float* __restrict__ wg){
    __shared__ float als[16][CDIM];
    int t = threadIdx.x; int m0 = blockIdx.x*16;
    int mat = blockIdx.y;
    int w = t >> 5, l = t & 31;
    for (int idx = t; idx < 16*CDIM; idx += 128){
        int r = idx >> 7, c = idx & 127;
        als[r][c] = g_a[(size_t)(m0+r)*CDIM + c];
    }
    __syncthreads();
    for (int r = 0; r < 4; r++){
        int i = w*4 + r; int n = m0 + i;
        float x0=als[i][l], x1=als[i][l+32], x2=als[i][l+64], x3=als[i][l+96];
        float s = x0+x1+x2+x3;
        float s2 = x0*x0+x1*x1+x2*x2+x3*x3;
        #pragma unroll
        for (int o = 16; o; o >>= 1){
            s  += __shfl_xor_sync(0xffffffffu, s, o);
            s2 += __shfl_xor_sync(0xffffffffu, s2, o);
        }
        float mean = s*(1.f/CDIM);
        float var  = s2*(1.f/CDIM) - mean*mean;
        float rstd = rsqrtf(var + EPS);
        float a0=(x0-mean)*rstd, a1=(x1-mean)*rstd, a2=(x2-mean)*rstd, a3=(x3-mean)*rstd;
        size_t nb = (size_t)n*CDIM;
        if (mat == 0){
            g_an[nb+l]=a0; g_an[nb+l+32]=a1; g_an[nb+l+64]=a2; g_an[nb+l+96]=a3;
        }
        als[i][l]    = gate1[nb+l]   *a0 + shift1[nb+l];
        als[i][l+32] = gate1[nb+l+32]*a1 + shift1[nb+l+32];
        als[i][l+64] = gate1[nb+l+64]*a2 + shift1[nb+l+64];
        als[i][l+96] = gate1[nb+l+96]*a3 + shift1[nb+l+96];
    }
    __syncthreads();
    const float* W; float* O;
    switch(mat){
        case 0: W = wq; O = g_q; break;
        case 1: W = wk; O = g_k; break;
        case 2: W = wv; O = g_v; break;
        default: W = wg; O = g_g; break;
    }
    float acc[16];
    #pragma unroll
    for (int i = 0; i < 16; i++) acc[i] = 0.f;
    #pragma unroll 4
    for (int k = 0; k < CDIM; k++){
        float wv_ = W[k*CDIM + t];
        #pragma unroll
        for (int i = 0; i < 16; i++) acc[i] += als[i][k]*wv_;
    }
    float bb = (mat == 0) ? bq[t] : 0.f;
    #pragma unroll
    for (int i = 0; i < 16; i++){
        float v = acc[i] + bb;
        if (mat == 3) v = sigm(v);
        O[(size_t)(m0+i)*CDIM + t] = v;
    }
}

// ---------------- block-sparse attention ----------------
__global__ void attn_kernel(const float* __restrict__ pb){
    __shared__ float qs[32][32];
    __shared__ float vs[128][32];
    __shared__ float buf[128*32];
    int t = threadIdx.x;
    int j = blockIdx.x, h = blockIdx.y;
    int n0 = j*NQ, w0 = j*NQ - 48, hd0 = h*CHD;
    for (int idx = t; idx < 32*32; idx += 128){
        int i = idx >> 5, d = idx & 31;
        qs[i][d] = g_q[(size_t)(n0+i)*CDIM + hd0 + d];
    }
    for (int idx = t; idx < 128*32; idx += 128){
        int m = idx >> 5, d = idx & 31;
        int key = w0 + m;
        float kk = 0.f, vv = 0.f;
        if (key >= 0 && key < NATOM){
            kk = g_k[(size_t)key*CDIM + hd0 + d];
            vv = g_v[(size_t)key*CDIM + hd0 + d];
        }
        buf[m*32 + d] = kk; vs[m][d] = vv;
    }
    __syncthreads();
    float kr[32];
    #pragma unroll
    for (int d = 0; d < 32; d++) kr[d] = buf[t*32 + d];
    __syncthreads();
    const float scale = 0.17677669529663687f;
    const float* pbr = pb + (size_t)h*NATOM*NKEY + (size_t)n0*NKEY;
    for (int i = 0; i < 32; i++){
        float acc = 0.f;
        #pragma unroll
        for (int d = 0; d < 32; d++) acc += qs[i][d]*kr[d];
        buf[i*128 + t] = acc*scale + pbr[i*NKEY + t];
    }
    __syncthreads();
    int w = t >> 5, l = t & 31;
    for (int r = 0; r < 8; r++){
        int i = w*8 + r;
        float x0=buf[i*128+l], x1=buf[i*128+l+32], x2=buf[i*128+l+64], x3=buf[i*128+l+96];
        float mx = fmaxf(fmaxf(x0,x1), fmaxf(x2,x3));
        #pragma unroll
        for (int o = 16; o; o >>= 1) mx = fmaxf(mx, __shfl_xor_sync(0xffffffffu, mx, o));
        float e0=expf(x0-mx), e1=expf(x1-mx), e2=expf(x2-mx), e3=expf(x3-mx);
        float s = e0+e1+e2+e3;
        #pragma unroll
        for (int o = 16; o; o >>= 1) s += __shfl_xor_sync(0xffffffffu, s, o);
        float inv = 1.f/s;
        buf[i*128+l]=e0*inv; buf[i*128+l+32]=e1*inv; buf[i*128+l+64]=e2*inv; buf[i*128+l+96]=e3*inv;
    }
    __syncthreads();
    int i = t >> 2, d0 = (t & 3)*8;
    float acc[8];
    #pragma unroll
    for (int dd = 0; dd < 8; dd++) acc[dd] = 0.f;
    #pragma unroll 4
    for (int kk = 0; kk < 128; kk++){
        float wgt = buf[i*128 + kk];
        #pragma unroll
        for (int dd = 0; dd < 8; dd++) acc[dd] += wgt*vs[kk][d0+dd];
    }
    int n = n0 + i;
    #pragma unroll
    for (int dd = 0; dd < 8; dd++){
        int c = hd0 + d0 + dd;
        g_ob[(size_t)n*CDIM + c] = g_g[(size_t)n*CDIM + c]*acc[dd];
    }
}

// ---------------- fused tail: outproj*og1 + SwiGLU transition + residual add --------
// grid 256 CTAs, 8 rows each, 256 threads.
__global__ void tail_kernel(const float* __restrict__ wo, const float* __restrict__ og1,
                            const float* __restrict__ gate2, const float* __restrict__ shift2,
                            const float* __restrict__ wt1, const float* __restrict__ wt2,
                            const float* __restrict__ wt3, const float* __restrict__ og2){
    __shared__ float obs[8][CDIM];
    __shared__ float a2s[8][CDIM];
    __shared__ float att[8][CDIM];
    __shared__ float hid[8][NHID];
    int t = threadIdx.x;               // 256 threads
    int m0 = blockIdx.x*8;
    // load ob and a2 rows
    for (int idx = t; idx < 8*CDIM; idx += 256){
        int r = idx >> 7, c = idx & 127;
        size_t o = (size_t)(m0+r)*CDIM + c;
        obs[r][c] = g_ob[o];
        a2s[r][c] = gate2[o]*g_an[o] + shift2[o];
    }
    __syncthreads();
    // phase A: outproj (128 cols), thread -> (col, half of rows)
    {
        int col = t & 127, half = t >> 7;
        int r0 = half*4;
        float acc[4] = {0.f,0.f,0.f,0.f};
        #pragma unroll 4
        for (int k = 0; k < CDIM; k++){
            float w = wo[k*CDIM + col];
            #pragma unroll
            for (int i = 0; i < 4; i++) acc[i] += obs[r0+i][k]*w;
        }
        #pragma unroll
        for (int i = 0; i < 4; i++){
            size_t o = (size_t)(m0+r0+i)*CDIM + col;
            att[r0+i][col] = og1[o]*acc[i];
        }
    }
    __syncthreads();
    // phase B: trans1 -> hidden (256 cols)
    {
        float acc1[8], acc2[8];
        #pragma unroll
        for (int i = 0; i < 8; i++){ acc1[i]=0.f; acc2[i]=0.f; }
        #pragma unroll 4
        for (int k = 0; k < CDIM; k++){
            float w1 = wt1[k*NHID + t], w2 = wt2[k*NHID + t];
            #pragma unroll
            for (int i = 0; i < 8; i++){
                float a = a2s[i][k];
                acc1[i] += a*w1; acc2[i] += a*w2;
            }
        }
        #pragma unroll
        for (int i = 0; i < 8; i++){
            float h1 = acc1[i];
            hid[i][t] = h1*sigm(h1)*acc2[i];
        }
    }
    __syncthreads();
    // phase C: trans2 (k=256) + og2 gate + residual add -> g_a
    {
        int col = t & 127, half = t >> 7;
        int r0 = half*4;
        float acc[4] = {0.f,0.f,0.f,0.f};
        #pragma unroll 4
        for (int k = 0; k < NHID; k++){
            float w = wt3[k*CDIM + col];
            #pragma unroll
            for (int i = 0; i < 4; i++) acc[i] += hid[r0+i][k]*w;
        }
        #pragma unroll
        for (int i = 0; i < 4; i++){
            size_t o = (size_t)(m0+r0+i)*CDIM + col;
            g_a[o] = att[r0+i][col] + og2[o]*acc[i];
        }
    }
}

// ---------------- host launcher ----------------
extern "C" void kernel_launch(void* const* d_in, const int* in_sizes, int n_in,
                              void* d_out, int out_size){
    const float* ql       = (const float*)d_in[0];
    const float* cl       = (const float*)d_in[1];
    const float* plm      = (const float*)d_in[2];
    const float* a2t      = (const float*)d_in[3];
    const float* tm       = (const float*)d_in[4];
    const float* ada1_gs  = (const float*)d_in[5];
    const float* ada1_ws  = (const float*)d_in[6];
    const float* ada1_bs  = (const float*)d_in[7];
    const float* ada1_wsb = (const float*)d_in[8];
    const float* wq       = (const float*)d_in[9];
    const float* bq       = (const float*)d_in[10];
    const float* wk       = (const float*)d_in[11];
    const float* wv       = (const float*)d_in[12];
    const float* gz       = (const float*)d_in[13];
    const float* bz       = (const float*)d_in[14];
    const float* wz       = (const float*)d_in[15];
    const float* wg       = (const float*)d_in[16];
    const float* wo       = (const float*)d_in[17];
    const float* wog1     = (const float*)d_in[18];
    const float* bog1     = (const float*)d_in[19];
    const float* ada2_gs  = (const float*)d_in[20];
    const float* ada2_ws  = (const float*)d_in[21];
    const float* ada2_bs  = (const float*)d_in[22];
    const float* ada2_wsb = (const float*)d_in[23];
    const float* wt1      = (const float*)d_in[24];
    const float* wt2      = (const float*)d_in[25];
    const float* wt3      = (const float*)d_in[26];
    const float* wog2     = (const float*)d_in[27];
    const float* bog2     = (const float*)d_in[28];

    float *p_lns, *p_gate1, *p_shift1, *p_gate2, *p_shift2, *p_og1, *p_og2, *p_pb;
    cudaGetSymbolAddress((void**)&p_lns,    g_lns);
    cudaGetSymbolAddress((void**)&p_gate1,  g_gate1);
    cudaGetSymbolAddress((void**)&p_shift1, g_shift1);
    cudaGetSymbolAddress((void**)&p_gate2,  g_gate2);
    cudaGetSymbolAddress((void**)&p_shift2, g_shift2);
    cudaGetSymbolAddress((void**)&p_og1,    g_og1);
    cudaGetSymbolAddress((void**)&p_og2,    g_og2);
    cudaGetSymbolAddress((void**)&p_pb,     g_pb);

    copy_in_kernel<<<NC/256, 256>>>(ql);
    ln_cl_kernel<<<NATOM/16, 128>>>(cl);
    maskbias_kernel<<<NATOM/8, 256>>>(a2t, tm);

    dim3 pg(NATOM/16, 18);
    pre_gemm_kernel<<<pg, 128>>>(p_lns, cl,
        ada1_gs, ada1_ws, ada1_bs, ada1_wsb,
        ada2_gs, ada2_ws, ada2_bs, ada2_wsb,
        wog1, bog1, wog2, bog2);

    pb_kernel<<<NATOM*NKEY/256, 256>>>(plm, gz, bz, wz);

    for (int b = 0; b < NBL; b++){
        size_t oC = (size_t)b*NC, oW = (size_t)b*CDIM*CDIM;
        dim3 qg(NATOM/16, 4);
        adaln_proj_kernel<<<qg, 128>>>(p_gate1+oC, p_shift1+oC,
                                       wq+oW, bq+(size_t)b*CDIM, wk+oW, wv+oW, wg+oW);
        dim3 ag(NQB, NHEADS);
        attn_kernel<<<ag, 128>>>(p_pb + (size_t)b*NHEADS*NATOM*NKEY);
        tail_kernel<<<NATOM/8, 256>>>(wo+oW, p_og1+oC, p_gate2+oC, p_shift2+oC,
                                      wt1+(size_t)b*CDIM*NHID, wt2+(size_t)b*CDIM*NHID,
                                      wt3+(size_t)b*NHID*CDIM, p_og2+oC);
    }
    copy_out_kernel<<<NC/256, 256>>>((float*)d_out);
}

// round 3
// speedup vs baseline: 2.4084x; 1.1524x over previous
#include <cuda_runtime.h>
#include <math.h>

#define NATOM 2048
#define NTOK  512
#define CDIM  128
#define CZD   16
#define NHEADS 4
#define CHD   32
#define NBL   3
#define NHID  256
#define NQ    32
#define NKEY  128
#define NQB   (NATOM/NQ)
#define EPS   1e-5f
#define NEGBIG -1e30f
#define NC    (NATOM*CDIM)

// ---------------- scratch ----------------
__device__ float g_maskbias[NATOM];
__device__ float g_lns[NC];
__device__ float g_gate1[NBL*NC];
__device__ float g_shift1[NBL*NC];
__device__ float g_gate2[NBL*NC];
__device__ float g_shift2[NBL*NC];
__device__ float g_og1[NBL*NC];
__device__ float g_og2[NBL*NC];
__device__ float g_pb[NBL*NHEADS*NATOM*NKEY];
__device__ float g_a[NC];
__device__ float g_an[NC];
__device__ float g_q[NC];
__device__ float g_k[NC];
__device__ float g_v[NC];
__device__ float g_g[NC];
__device__ float g_ob[NC];

__device__ __forceinline__ float sigm(float x){ return 1.f/(1.f+expf(-x)); }

// ---------------- copy in/out ----------------
__global__ void copy_in_kernel(const float* __restrict__ src){
    int i = blockIdx.x*256 + threadIdx.x;
    g_a[i] = src[i];
}
__global__ void copy_out_kernel(float* __restrict__ dst){
    int i = blockIdx.x*256 + threadIdx.x;
    dst[i] = g_a[i];
}

// ---------------- mask bias ----------------
__global__ void maskbias_kernel(const float* __restrict__ a2t, const float* __restrict__ tm){
    int w = threadIdx.x >> 5, l = threadIdx.x & 31;
    int n = blockIdx.x*8 + w;
    const float* row = a2t + (size_t)n*NTOK;
    float s = 0.f;
    for (int i = l; i < NTOK; i += 32) s += row[i]*tm[i];
    #pragma unroll
    for (int o = 16; o; o >>= 1) s += __shfl_xor_sync(0xffffffffu, s, o);
    if (l == 0) g_maskbias[n] = (s - 1.0f)*1e9f;
}

// ---------------- LN(cl) ----------------
__global__ void ln_cl_kernel(const float* __restrict__ in){
    int w = threadIdx.x >> 5, l = threadIdx.x & 31;
    int base = blockIdx.x*16 + w*4;
    for (int r = 0; r < 4; r++){
        const float* row = in + (size_t)(base+r)*CDIM;
        float x0=row[l], x1=row[l+32], x2=row[l+64], x3=row[l+96];
        float s = x0+x1+x2+x3;
        float s2 = x0*x0+x1*x1+x2*x2+x3*x3;
        #pragma unroll
        for (int o = 16; o; o >>= 1){
            s  += __shfl_xor_sync(0xffffffffu, s, o);
            s2 += __shfl_xor_sync(0xffffffffu, s2, o);
        }
        float mean = s*(1.f/CDIM);
        float var  = s2*(1.f/CDIM) - mean*mean;
        float rstd = rsqrtf(var + EPS);
        float* orow = g_lns + (size_t)(base+r)*CDIM;
        orow[l]    = (x0-mean)*rstd;
        orow[l+32] = (x1-mean)*rstd;
        orow[l+64] = (x2-mean)*rstd;
        orow[l+96] = (x3-mean)*rstd;
    }
}

// ---------------- batched precompute: 18 GEMMs in ONE launch, LDS.128 inner loop ----
__global__ void pre_gemm_kernel(const float* __restrict__ lns, const float* __restrict__ cl,
    const float* __restrict__ a1gs, const float* __restrict__ a1ws,
    const float* __restrict__ a1bs, const float* __restrict__ a1wsb,
    const float* __restrict__ a2gs, const float* __restrict__ a2ws,
    const float* __restrict__ a2bs, const float* __restrict__ a2wsb,
    const float* __restrict__ wog1, const float* __restrict__ bog1,
    const float* __restrict__ wog2, const float* __restrict__ bog2)
{
    int my = blockIdx.y;
    int b = my/6, m = my%6;
    size_t oW = (size_t)b*CDIM*CDIM, o1 = (size_t)b*CDIM, oC = (size_t)b*NC;
    const float* in = lns; const float* gs = 0; const float* W = 0;
    const float* bias = 0; float* out = 0; int sig = 0;
    switch(m){
        case 0: gs=a1gs+o1; W=a1ws +oW; bias=a1bs+o1; sig=1; out=g_gate1 +oC; break;
        case 1: gs=a1gs+o1; W=a1wsb+oW;               sig=0; out=g_shift1+oC; break;
        case 2: gs=a2gs+o1; W=a2ws +oW; bias=a2bs+o1; sig=1; out=g_gate2 +oC; break;
        case 3: gs=a2gs+o1; W=a2wsb+oW;               sig=0; out=g_shift2+oC; break;
        case 4: in=cl; W=wog1+oW; bias=bog1+o1; sig=1; out=g_og1+oC; break;
        default: in=cl; W=wog2+oW; bias=bog2+o1; sig=1; out=g_og2+oC; break;
    }
    __shared__ float ins[16][CDIM];
    int t = threadIdx.x; int m0 = blockIdx.x*16;
    const float4* in4 = (const float4*)in;
    const float4* gs4 = (const float4*)gs;
    for (int idx = t; idx < 16*32; idx += 128){
        int r = idx >> 5, c4 = idx & 31;
        float4 v = in4[(size_t)(m0+r)*32 + c4];
        if (gs){ float4 g = gs4[c4]; v.x*=g.x; v.y*=g.y; v.z*=g.z; v.w*=g.w; }
        *(float4*)&ins[r][c4*4] = v;
    }
    __syncthreads();
    float acc[16];
    #pragma unroll
    for (int i = 0; i < 16; i++) acc[i] = 0.f;
    #pragma unroll 2
    for (int k4 = 0; k4 < CDIM/4; k4++){
        float w0 = W[(k4*4+0)*CDIM + t];
        float w1 = W[(k4*4+1)*CDIM + t];
        float w2 = W[(k4*4+2)*CDIM + t];
        float w3 = W[(k4*4+3)*CDIM + t];
        #pragma unroll
        for (int i = 0; i < 16; i++){
            float4 a = *(const float4*)&ins[i][k4*4];
            acc[i] = fmaf(a.x, w0, fmaf(a.y, w1, fmaf(a.z, w2, fmaf(a.w, w3, acc[i]))));
        }
    }
    float bb = bias ? bias[t] : 0.f;
    #pragma unroll
    for (int i = 0; i < 16; i++){
        float v = acc[i] + bb;
        if (sig) v = sigm(v);
        out[(size_t)(m0+i)*CDIM + t] = v;
    }
}

// ---------------- pair bias (mask + window folded) ----------------
__global__ void pb_kernel(const float* __restrict__ plm, const float* __restrict__ gz,
                          const float* __restrict__ bz, const float* __restrict__ wz){
    __shared__ float wzc[CZD][12];
    __shared__ float bzd[12];
    int t = threadIdx.x;
    if (t < CZD*12){
        int c = t/12, idx = t%12, b = idx>>2, h = idx&3;
        wzc[c][idx] = gz[b*CZD + c]*wz[(b*CZD + c)*4 + h];
    }
    if (t < 12){
        int b = t>>2, h = t&3; float s = 0.f;
        for (int c = 0; c < CZD; c++) s += bz[b*CZD + c]*wz[(b*CZD + c)*4 + h];
        bzd[t] = s;
    }
    __syncthreads();
    int gid = blockIdx.x*256 + t;
    int n = gid >> 7, slot = gid & 127;
    int m = (n & ~31) - 48 + slot;
    if (m < 0 || m >= NATOM){
        #pragma unroll
        for (int idx = 0; idx < 12; idx++)
            g_pb[((size_t)idx*NATOM + n)*NKEY + slot] = NEGBIG;
        return;
    }
    const float4* p = (const float4*)(plm + ((size_t)n*NATOM + m)*CZD);
    float x[16];
    float4 f;
    f = p[0]; x[0]=f.x; x[1]=f.y; x[2]=f.z; x[3]=f.w;
    f = p[1]; x[4]=f.x; x[5]=f.y; x[6]=f.z; x[7]=f.w;
    f = p[2]; x[8]=f.x; x[9]=f.y; x[10]=f.z; x[11]=f.w;
    f = p[3]; x[12]=f.x; x[13]=f.y; x[14]=f.z; x[15]=f.w;
    float s = 0.f, s2 = 0.f;
    #pragma unroll
    for (int c = 0; c < 16; c++){ s += x[c]; s2 += x[c]*x[c]; }
    float mean = s*(1.f/16.f);
    float var  = s2*(1.f/16.f) - mean*mean;
    float rstd = rsqrtf(var + EPS);
    float val[12];
    #pragma unroll
    for (int idx = 0; idx < 12; idx++) val[idx] = 0.f;
    #pragma unroll
    for (int c = 0; c < 16; c++){
        float z = (x[c]-mean)*rstd;
        #pragma unroll
        for (int idx = 0; idx < 12; idx++) val[idx] += z*wzc[c][idx];
    }
    float mb = g_maskbias[m];
    #pragma unroll
    for (int idx = 0; idx < 12; idx++)
        g_pb[((size_t)idx*NATOM + n)*NKEY + slot] = val[idx] + bzd[idx] + mb;
}

// ---------------- per-block: fused AdaLN + one of {q,k,v,g} projections ------------
__global__ void adaln_proj_kernel(const float* __restrict__ gate1, const float* __restrict__ shift1,
                                  const float* __restrict__ wq, const float* __restrict__ bq,
                                  const float* __restrict__ wk, const float* __restrict__ wv,
                                  const float* __restrict__ wg){
    __shared__ float als[16][CDIM];
    int t = threadIdx.x; int m0 = blockIdx.x*16;
    int mat = blockIdx.y;
    int w = t >> 5, l = t & 31;
    for (int idx = t; idx < 16*CDIM; idx += 128){
        int r = idx >> 7, c = idx & 127;
        als[r][c] = g_a[(size_t)(m0+r)*CDIM + c];
    }
    __syncthreads();
    for (int r = 0; r < 4; r++){
        int i = w*4 + r; int n = m0 + i;
        float x0=als[i][l], x1=als[i][l+32], x2=als[i][l+64], x3=als[i][l+96];
        float s = x0+x1+x2+x3;
        float s2 = x0*x0+x1*x1+x2*x2+x3*x3;
        #pragma unroll
        for (int o = 16; o; o >>= 1){
            s  += __shfl_xor_sync(0xffffffffu, s, o);
            s2 += __shfl_xor_sync(0xffffffffu, s2, o);
        }
        float mean = s*(1.f/CDIM);
        float var  = s2*(1.f/CDIM) - mean*mean;
        float rstd = rsqrtf(var + EPS);
        float a0=(x0-mean)*rstd, a1=(x1-mean)*rstd, a2=(x2-mean)*rstd, a3=(x3-mean)*rstd;
        size_t nb = (size_t)n*CDIM;
        if (mat == 0){
            g_an[nb+l]=a0; g_an[nb+l+32]=a1; g_an[nb+l+64]=a2; g_an[nb+l+96]=a3;
        }
        als[i][l]    = gate1[nb+l]   *a0 + shift1[nb+l];
        als[i][l+32] = gate1[nb+l+32]*a1 + shift1[nb+l+32];
        als[i][l+64] = gate1[nb+l+64]*a2 + shift1[nb+l+64];
        als[i][l+96] = gate1[nb+l+96]*a3 + shift1[nb+l+96];
    }
    __syncthreads();
    const float* W; float* O;
    switch(mat){
        case 0: W = wq; O = g_q; break;
        case 1: W = wk; O = g_k; break;
        case 2: W = wv; O = g_v; break;
        default: W = wg; O = g_g; break;
    }
    float acc[16];
    #pragma unroll
    for (int i = 0; i < 16; i++) acc[i] = 0.f;
    #pragma unroll 2
    for (int k4 = 0; k4 < CDIM/4; k4++){
        float w0 = W[(k4*4+0)*CDIM + t];
        float w1 = W[(k4*4+1)*CDIM + t];
        float w2 = W[(k4*4+2)*CDIM + t];
        float w3 = W[(k4*4+3)*CDIM + t];
        #pragma unroll
        for (int i = 0; i < 16; i++){
            float4 a = *(const float4*)&als[i][k4*4];
            acc[i] = fmaf(a.x, w0, fmaf(a.y, w1, fmaf(a.z, w2, fmaf(a.w, w3, acc[i]))));
        }
    }
    float bb = (mat == 0) ? bq[t] : 0.f;
    #pragma unroll
    for (int i = 0; i < 16; i++){
        float v = acc[i] + bb;
        if (mat == 3) v = sigm(v);
        O[(size_t)(m0+i)*CDIM + t] = v;
    }
}

// ---------------- block-sparse attention ----------------
__global__ void attn_kernel(const float* __restrict__ pb){
    __shared__ float qs[32][32];
    __shared__ float vs[128][32];
    __shared__ float buf[128*32];
    int t = threadIdx.x;
    int j = blockIdx.x, h = blockIdx.y;
    int n0 = j*NQ, w0 = j*NQ - 48, hd0 = h*CHD;
    for (int idx = t; idx < 32*32; idx += 128){
        int i = idx >> 5, d = idx & 31;
        qs[i][d] = g_q[(size_t)(n0+i)*CDIM + hd0 + d];
    }
    for (int idx = t; idx < 128*32; idx += 128){
        int m = idx >> 5, d = idx & 31;
        int key = w0 + m;
        float kk = 0.f, vv = 0.f;
        if (key >= 0 && key < NATOM){
            kk = g_k[(size_t)key*CDIM + hd0 + d];
            vv = g_v[(size_t)key*CDIM + hd0 + d];
        }
        buf[m*32 + d] = kk; vs[m][d] = vv;
    }
    __syncthreads();
    float kr[32];
    #pragma unroll
    for (int d = 0; d < 32; d++) kr[d] = buf[t*32 + d];
    __syncthreads();
    const float scale = 0.17677669529663687f;
    const float* pbr = pb + (size_t)h*NATOM*NKEY + (size_t)n0*NKEY;
    #pragma unroll 4
    for (int i = 0; i < 32; i++){
        float acc = 0.f;
        #pragma unroll
        for (int d4 = 0; d4 < 8; d4++){
            float4 q = *(const float4*)&qs[i][d4*4];
            acc = fmaf(q.x, kr[d4*4+0], fmaf(q.y, kr[d4*4+1],
                  fmaf(q.z, kr[d4*4+2], fmaf(q.w, kr[d4*4+3], acc))));
        }
        buf[i*128 + t] = acc*scale + pbr[i*NKEY + t];
    }
    __syncthreads();
    int w = t >> 5, l = t & 31;
    for (int r = 0; r < 8; r++){
        int i = w*8 + r;
        float x0=buf[i*128+l], x1=buf[i*128+l+32], x2=buf[i*128+l+64], x3=buf[i*128+l+96];
        float mx = fmaxf(fmaxf(x0,x1), fmaxf(x2,x3));
        #pragma unroll
        for (int o = 16; o; o >>= 1) mx = fmaxf(mx, __shfl_xor_sync(0xffffffffu, mx, o));
        float e0=expf(x0-mx), e1=expf(x1-mx), e2=expf(x2-mx), e3=expf(x3-mx);
        float s = e0+e1+e2+e3;
        #pragma unroll
        for (int o = 16; o; o >>= 1) s += __shfl_xor_sync(0xffffffffu, s, o);
        float inv = 1.f/s;
        buf[i*128+l]=e0*inv; buf[i*128+l+32]=e1*inv; buf[i*128+l+64]=e2*inv; buf[i*128+l+96]=e3*inv;
    }
    __syncthreads();
    int i = t >> 2, d0 = (t & 3)*8;
    float acc[8];
    #pragma unroll
    for (int dd = 0; dd < 8; dd++) acc[dd] = 0.f;
    #pragma unroll 4
    for (int kk = 0; kk < 128; kk++){
        float wgt = buf[i*128 + kk];
        float4 v0 = *(const float4*)&vs[kk][d0];
        float4 v1 = *(const float4*)&vs[kk][d0+4];
        acc[0] = fmaf(wgt, v0.x, acc[0]); acc[1] = fmaf(wgt, v0.y, acc[1]);
        acc[2] = fmaf(wgt, v0.z, acc[2]); acc[3] = fmaf(wgt, v0.w, acc[3]);
        acc[4] = fmaf(wgt, v1.x, acc[4]); acc[5] = fmaf(wgt, v1.y, acc[5]);
        acc[6] = fmaf(wgt, v1.z, acc[6]); acc[7] = fmaf(wgt, v1.w, acc[7]);
    }
    int n = n0 + i;
    #pragma unroll
    for (int dd = 0; dd < 8; dd++){
        int c = hd0 + d0 + dd;
        g_ob[(size_t)n*CDIM + c] = g_g[(size_t)n*CDIM + c]*acc[dd];
    }
}

// ---------------- fused tail ----------------
__global__ void tail_kernel(const float* __restrict__ wo, const float* __restrict__ og1,
                            const float* __restrict__ gate2, const float* __restrict__ shift2,
                            const float* __restrict__ wt1, const float* __restrict__ wt2,
                            const float* __restrict__ wt3, const float* __restrict__ og2){
    __shared__ float obs[8][CDIM];
    __shared__ float a2s[8][CDIM];
    __shared__ float att[8][CDIM];
    __shared__ float hid[8][NHID];
    int t = threadIdx.x;               // 256
    int m0 = blockIdx.x*8;
    for (int idx = t; idx < 8*CDIM; idx += 256){
        int r = idx >> 7, c = idx & 127;
        size_t o = (size_t)(m0+r)*CDIM + c;
        obs[r][c] = g_ob[o];
        a2s[r][c] = gate2[o]*g_an[o] + shift2[o];
    }
    __syncthreads();
    // phase A: outproj
    {
        int col = t & 127, half = t >> 7;
        int r0 = half*4;
        float acc[4] = {0.f,0.f,0.f,0.f};
        #pragma unroll 2
        for (int k4 = 0; k4 < CDIM/4; k4++){
            float w0 = wo[(k4*4+0)*CDIM + col];
            float w1 = wo[(k4*4+1)*CDIM + col];
            float w2 = wo[(k4*4+2)*CDIM + col];
            float w3 = wo[(k4*4+3)*CDIM + col];
            #pragma unroll
            for (int i = 0; i < 4; i++){
                float4 a = *(const float4*)&obs[r0+i][k4*4];
                acc[i] = fmaf(a.x, w0, fmaf(a.y, w1, fmaf(a.z, w2, fmaf(a.w, w3, acc[i]))));
            }
        }
        #pragma unroll
        for (int i = 0; i < 4; i++){
            size_t o = (size_t)(m0+r0+i)*CDIM + col;
            att[r0+i][col] = og1[o]*acc[i];
        }
    }
    __syncthreads();
    // phase B: trans1 -> hidden
    {
        float acc1[8], acc2[8];
        #pragma unroll
        for (int i = 0; i < 8; i++){ acc1[i]=0.f; acc2[i]=0.f; }
        #pragma unroll 2
        for (int k4 = 0; k4 < CDIM/4; k4++){
            float w10 = wt1[(k4*4+0)*NHID + t], w20 = wt2[(k4*4+0)*NHID + t];
            float w11 = wt1[(k4*4+1)*NHID + t], w21 = wt2[(k4*4+1)*NHID + t];
            float w12 = wt1[(k4*4+2)*NHID + t], w22 = wt2[(k4*4+2)*NHID + t];
            float w13 = wt1[(k4*4+3)*NHID + t], w23 = wt2[(k4*4+3)*NHID + t];
            #pragma unroll
            for (int i = 0; i < 8; i++){
                float4 a = *(const float4*)&a2s[i][k4*4];
                acc1[i] = fmaf(a.x, w10, fmaf(a.y, w11, fmaf(a.z, w12, fmaf(a.w, w13, acc1[i]))));
                acc2[i] = fmaf(a.x, w20, fmaf(a.y, w21, fmaf(a.z, w22, fmaf(a.w, w23, acc2[i]))));
            }
        }
        #pragma unroll
        for (int i = 0; i < 8; i++){
            float h1 = acc1[i];
            hid[i][t] = h1*sigm(h1)*acc2[i];
        }
    }
    __syncthreads();
    // phase C: trans2 + og2 gate + residual
    {
        int col = t & 127, half = t >> 7;
        int r0 = half*4;
        float acc[4] = {0.f,0.f,0.f,0.f};
        #pragma unroll 2
        for (int k4 = 0; k4 < NHID/4; k4++){
            float w0 = wt3[(k4*4+0)*CDIM + col];
            float w1 = wt3[(k4*4+1)*CDIM + col];
            float w2 = wt3[(k4*4+2)*CDIM + col];
            float w3 = wt3[(k4*4+3)*CDIM + col];
            #pragma unroll
            for (int i = 0; i < 4; i++){
                float4 a = *(const float4*)&hid[r0+i][k4*4];
                acc[i] = fmaf(a.x, w0, fmaf(a.y, w1, fmaf(a.z, w2, fmaf(a.w, w3, acc[i]))));
            }
        }
        #pragma unroll
        for (int i = 0; i < 4; i++){
            size_t o = (size_t)(m0+r0+i)*CDIM + col;
            g_a[o] = att[r0+i][col] + og2[o]*acc[i];
        }
    }
}

// ---------------- host launcher ----------------
extern "C" void kernel_launch(void* const* d_in, const int* in_sizes, int n_in,
                              void* d_out, int out_size){
    const float* ql       = (const float*)d_in[0];
    const float* cl       = (const float*)d_in[1];
    const float* plm      = (const float*)d_in[2];
    const float* a2t      = (const float*)d_in[3];
    const float* tm       = (const float*)d_in[4];
    const float* ada1_gs  = (const float*)d_in[5];
    const float* ada1_ws  = (const float*)d_in[6];
    const float* ada1_bs  = (const float*)d_in[7];
    const float* ada1_wsb = (const float*)d_in[8];
    const float* wq       = (const float*)d_in[9];
    const float* bq       = (const float*)d_in[10];
    const float* wk       = (const float*)d_in[11];
    const float* wv       = (const float*)d_in[12];
    const float* gz       = (const float*)d_in[13];
    const float* bz       = (const float*)d_in[14];
    const float* wz       = (const float*)d_in[15];
    const float* wg       = (const float*)d_in[16];
    const float* wo       = (const float*)d_in[17];
    const float* wog1     = (const float*)d_in[18];
    const float* bog1     = (const float*)d_in[19];
    const float* ada2_gs  = (const float*)d_in[20];
    const float* ada2_ws  = (const float*)d_in[21];
    const float* ada2_bs  = (const float*)d_in[22];
    const float* ada2_wsb = (const float*)d_in[23];
    const float* wt1      = (const float*)d_in[24];
    const float* wt2      = (const float*)d_in[25];
    const float* wt3      = (const float*)d_in[26];
    const float* wog2     = (const float*)d_in[27];
    const float* bog2     = (const float*)d_in[28];

    float *p_lns, *p_gate1, *p_shift1, *p_gate2, *p_shift2, *p_og1, *p_og2, *p_pb;
    cudaGetSymbolAddress((void**)&p_lns,    g_lns);
    cudaGetSymbolAddress((void**)&p_gate1,  g_gate1);
    cudaGetSymbolAddress((void**)&p_shift1, g_shift1);
    cudaGetSymbolAddress((void**)&p_gate2,  g_gate2);
    cudaGetSymbolAddress((void**)&p_shift2, g_shift2);
    cudaGetSymbolAddress((void**)&p_og1,    g_og1);
    cudaGetSymbolAddress((void**)&p_og2,    g_og2);
    cudaGetSymbolAddress((void**)&p_pb,     g_pb);

    copy_in_kernel<<<NC/256, 256>>>(ql);
    ln_cl_kernel<<<NATOM/16, 128>>>(cl);
    maskbias_kernel<<<NATOM/8, 256>>>(a2t, tm);

    dim3 pg(NATOM/16, 18);
    pre_gemm_kernel<<<pg, 128>>>(p_lns, cl,
        ada1_gs, ada1_ws, ada1_bs, ada1_wsb,
        ada2_gs, ada2_ws, ada2_bs, ada2_wsb,
        wog1, bog1, wog2, bog2);

    pb_kernel<<<NATOM*NKEY/256, 256>>>(plm, gz, bz, wz);

    for (int b = 0; b < NBL; b++){
        size_t oC = (size_t)b*NC, oW = (size_t)b*CDIM*CDIM;
        dim3 qg(NATOM/16, 4);
        adaln_proj_kernel<<<qg, 128>>>(p_gate1+oC, p_shift1+oC,
                                       wq+oW, bq+(size_t)b*CDIM, wk+oW, wv+oW, wg+oW);
        dim3 ag(NQB, NHEADS);
        attn_kernel<<<ag, 128>>>(p_pb + (size_t)b*NHEADS*NATOM*NKEY);
        tail_kernel<<<NATOM/8, 256>>>(wo+oW, p_og1+oC, p_gate2+oC, p_shift2+oC,
                                      wt1+(size_t)b*CDIM*NHID, wt2+(size_t)b*CDIM*NHID,
                                      wt3+(size_t)b*NHID*CDIM, p_og2+oC);
    }
    copy_out_kernel<<<NC/256, 256>>>((float*)d_out);
}